// round 13
// baseline (speedup 1.0000x reference)
#include <cuda_runtime.h>
#include <cuda_bf16.h>
#include <cuda_fp16.h>
#include <float.h>
#include <stdint.h>

#define D_DIM   64
#define K_CODES 512
#define BLOCK   512          // 16 warps: 2 row-groups x 8 code-eighths
#define GRID    296          // 2 CTAs per SM
#define NROWS   65536
#define TILE    32           // rows per tile
#define NTILES  2048
#define CAP     16           // worklist slots per row

// ---- SMEM layout (bytes), per CTA ~70KB -> 2 CTAs/SM ----
#define SM_BH    0            // 8192 uint2 hi-bf16 B fragments (64KB)
#define SM_SN    65536        // 512 floats: exact ||e_k||^2
#define SM_SMIN  67584        // 8*32 floats: per-eighth row min
#define SM_SXN   68608        // 32 floats: ||x_r||^2
#define SM_SRX   68736        // 32 floats: ||x_r - xh_r||^2
#define SM_STHR  68864        // 32 floats: per-row threshold
#define SM_RCNT  68992        // 32 ints
#define SM_RBEST 69120        // 32 u64
#define SM_WL    69376        // 32*CAP ints (2KB)
#define SM_SE2   71424        // int
#define SM_SH2   71428        // int
#define SM_LS    71432        // 16 doubles
#define SMEM_TOTAL 71560

__device__ float        g_embT[K_CODES * D_DIM];   // exact fp32 codebook [k][d]
__device__ double       g_partial[GRID];
__device__ unsigned int g_cnt = 0;

#define MMA(acc, a, b0, b1)                                                     \
    asm volatile(                                                               \
        "mma.sync.aligned.m16n8k16.row.col.f32.bf16.bf16.f32 "                  \
        "{%0,%1,%2,%3}, {%4,%5,%6,%7}, {%8,%9}, {%0,%1,%2,%3};"                 \
        : "+f"((acc)[0]), "+f"((acc)[1]), "+f"((acc)[2]), "+f"((acc)[3])        \
        : "r"((a)[0]), "r"((a)[1]), "r"((a)[2]), "r"((a)[3]), "r"(b0), "r"(b1))

__device__ __forceinline__ uint32_t pack_bf2(float a, float b) {
    return (uint32_t)__bfloat16_as_ushort(__float2bfloat16(a))
         | ((uint32_t)__bfloat16_as_ushort(__float2bfloat16(b)) << 16);
}

// exact fp32 squared distance row(x) vs code k (fixed summation order)
__device__ __forceinline__ float exact_dist(const float* __restrict__ xrow, int k) {
    const float4* xp = (const float4*)xrow;
    const float4* ep = (const float4*)(g_embT + k * D_DIM);
    float s = 0.f;
    #pragma unroll
    for (int j = 0; j < 16; j++) {
        float4 a = xp[j];
        float4 b = ep[j];
        float dx = a.x - b.x, dy = a.y - b.y, dz = a.z - b.z, dw = a.w - b.w;
        s = fmaf(dx, dx, s); s = fmaf(dy, dy, s);
        s = fmaf(dz, dz, s); s = fmaf(dw, dw, s);
    }
    return s;
}

// test one packed half2 estimate vs threshold; append passing codes (rare path)
__device__ __forceinline__ void test_h2(uint32_t h2bits, __half2 thr2, int kbase,
                                        int row, int* rcnt, int* swl) {
    __half2 v  = *(__half2*)&h2bits;
    __half2 le = __hle2(v, thr2);
    uint32_t m = *(uint32_t*)&le;
    if (m) {
        if (m & 0xFFFFu) {
            int s = atomicAdd(&rcnt[row], 1);
            if (s < CAP) swl[row * CAP + s] = kbase;
        }
        if (m >> 16) {
            int s = atomicAdd(&rcnt[row], 1);
            if (s < CAP) swl[row * CAP + s] = kbase + 1;
        }
    }
}

__global__ void __launch_bounds__(BLOCK, 2)
vq_2stage(const float* __restrict__ x, const float* __restrict__ emb,
          float* __restrict__ out, int write_loss)
{
    extern __shared__ char smem[];
    uint2*              sBH   = (uint2*)(smem + SM_BH);
    float*              snm   = (float*)(smem + SM_SN);
    float*              smin  = (float*)(smem + SM_SMIN);
    float*              sxn   = (float*)(smem + SM_SXN);
    float*              srx   = (float*)(smem + SM_SRX);
    float*              sthr  = (float*)(smem + SM_STHR);
    int*                rcnt  = (int*)(smem + SM_RCNT);
    unsigned long long* rbest = (unsigned long long*)(smem + SM_RBEST);
    int*                swl   = (int*)(smem + SM_WL);
    int*                sSE2  = (int*)(smem + SM_SE2);
    int*                sSH2  = (int*)(smem + SM_SH2);
    double*             sls   = (double*)(smem + SM_LS);

    const int tid  = threadIdx.x;
    const int w    = tid >> 5;
    const int lane = tid & 31;
    const int g    = lane >> 2;
    const int c    = lane & 3;
    const int rg   = w & 1;      // row-group (16 rows)
    const int ne   = w >> 1;     // code-eighth: [ne*64, +64)

    if (tid < 2) { sSE2[0] = 0; sSH2[0] = 0; }
    __syncthreads();

    // ---- Prologue 1: hi-bf16 B fragments -> SMEM + exact fp32 transpose ----
    for (int i = tid; i < 8192; i += BLOCK) {
        int nt = i >> 7;
        int ks = (i >> 5) & 3;
        int ln = i & 31;
        int fg = ln >> 2, fc = ln & 3;
        int n  = nt * 8 + fg;
        int d0 = ks * 16 + fc * 2;
        float e00 = __ldg(emb + (d0 + 0) * K_CODES + n);
        float e01 = __ldg(emb + (d0 + 1) * K_CODES + n);
        float e10 = __ldg(emb + (d0 + 8) * K_CODES + n);
        float e11 = __ldg(emb + (d0 + 9) * K_CODES + n);
        sBH[i] = make_uint2(pack_bf2(e00, e01), pack_bf2(e10, e11));
        g_embT[n * D_DIM + d0]     = e00;
        g_embT[n * D_DIM + d0 + 1] = e01;
        g_embT[n * D_DIM + d0 + 8] = e10;
        g_embT[n * D_DIM + d0 + 9] = e11;
    }
    // ---- Prologue 2: exact code norms + split-error maxima ----
    {
        const int k = tid;   // 512 == BLOCK
        float sn = 0.f, se = 0.f, sh = 0.f;
        #pragma unroll 8
        for (int d = 0; d < D_DIM; d++) {
            float v = emb[d * K_CODES + k];
            float h = __bfloat162float(__float2bfloat16(v));
            float r = v - h;
            sn = fmaf(v, v, sn);
            se = fmaf(r, r, se);
            sh = fmaf(h, h, sh);
        }
        snm[k] = sn;
        atomicMax(sSE2, __float_as_int(se));   // nonneg: int cmp == float cmp
        atomicMax(sSH2, __float_as_int(sh));
    }
    __syncthreads();

    const float S_e = sqrtf(__int_as_float(*sSE2)) * 1.0001f;  // max ||e-eh||
    const float S_h = sqrtf(__int_as_float(*sSH2)) * 1.0001f;  // max ||eh||

    double lacc = 0.0;

    for (int tile = blockIdx.x; tile < NTILES; tile += GRID) {
        const int rbase = tile * TILE + rg * 16 + g;

        if (tid < TILE) { rcnt[tid] = 0; rbest[tid] = ~0ull; }

        // ---- A fragments (hi split) + per-row norm / residual-norm ----
        uint32_t Ah[4][4];
        float xn0 = 0.f, xn1 = 0.f, rx0 = 0.f, rx1 = 0.f;
        {
            const float* xr0 = x + (size_t)rbase * D_DIM;
            const float* xr1 = xr0 + 8 * D_DIM;
            #pragma unroll
            for (int ks = 0; ks < 4; ks++) {
                #pragma unroll
                for (int p = 0; p < 2; p++) {
                    int col = 2 * c + 8 * p + 16 * ks;
                    float2 v0 = *(const float2*)(xr0 + col);
                    float2 v1 = *(const float2*)(xr1 + col);
                    xn0 = fmaf(v0.x, v0.x, fmaf(v0.y, v0.y, xn0));
                    xn1 = fmaf(v1.x, v1.x, fmaf(v1.y, v1.y, xn1));
                    float h0x = __bfloat162float(__float2bfloat16(v0.x));
                    float h0y = __bfloat162float(__float2bfloat16(v0.y));
                    float h1x = __bfloat162float(__float2bfloat16(v1.x));
                    float h1y = __bfloat162float(__float2bfloat16(v1.y));
                    float r0x = v0.x - h0x, r0y = v0.y - h0y;
                    float r1x = v1.x - h1x, r1y = v1.y - h1y;
                    rx0 = fmaf(r0x, r0x, fmaf(r0y, r0y, rx0));
                    rx1 = fmaf(r1x, r1x, fmaf(r1y, r1y, rx1));
                    Ah[ks][2 * p]     = pack_bf2(v0.x, v0.y);
                    Ah[ks][2 * p + 1] = pack_bf2(v1.x, v1.y);
                }
            }
        }
        #pragma unroll
        for (int off = 1; off <= 2; off <<= 1) {
            xn0 += __shfl_xor_sync(0xffffffffu, xn0, off);
            xn1 += __shfl_xor_sync(0xffffffffu, xn1, off);
            rx0 += __shfl_xor_sync(0xffffffffu, rx0, off);
            rx1 += __shfl_xor_sync(0xffffffffu, rx1, off);
        }
        if (c == 0 && ne == 0) {
            const int r = rg * 16 + g;
            sxn[r] = xn0;  sxn[r + 8] = xn1;
            srx[r] = rx0;  srx[r + 8] = rx1;
        }

        // ---- Stage A: est distances (hi-hi term) -> REGISTERS + row min ----
        uint32_t estp[16];           // 8 nt x {row r0 pair, row r0+8 pair}
        float m0 = FLT_MAX, m1 = FLT_MAX;
        const int ntbeg = ne * 8;
        #pragma unroll
        for (int j0 = 0; j0 < 8; j0 += 2) {
            float acc[2][4];
            #pragma unroll
            for (int u = 0; u < 2; u++)
                #pragma unroll
                for (int r = 0; r < 4; r++) acc[u][r] = 0.f;

            #pragma unroll
            for (int ks = 0; ks < 4; ks++)
                #pragma unroll
                for (int u = 0; u < 2; u++) {
                    uint2 b = sBH[((ntbeg + j0 + u) * 4 + ks) * 32 + lane];
                    MMA(acc[u], Ah[ks], b.x, b.y);
                }

            #pragma unroll
            for (int u = 0; u < 2; u++) {
                const int kb = (ntbeg + j0 + u) * 8 + 2 * c;
                float2 s2 = *(const float2*)(snm + kb);
                float e00 = fmaf(-2.f, acc[u][0], s2.x);
                float e01 = fmaf(-2.f, acc[u][1], s2.y);
                float e10 = fmaf(-2.f, acc[u][2], s2.x);
                float e11 = fmaf(-2.f, acc[u][3], s2.y);
                m0 = fminf(m0, fminf(e00, e01));
                m1 = fminf(m1, fminf(e10, e11));
                __half2 p0 = __floats2half2_rn(e00, e01);
                __half2 p1 = __floats2half2_rn(e10, e11);
                estp[2 * (j0 + u)]     = *(uint32_t*)&p0;
                estp[2 * (j0 + u) + 1] = *(uint32_t*)&p1;
            }
        }
        #pragma unroll
        for (int off = 1; off <= 2; off <<= 1) {
            m0 = fminf(m0, __shfl_xor_sync(0xffffffffu, m0, off));
            m1 = fminf(m1, __shfl_xor_sync(0xffffffffu, m1, off));
        }
        if (c == 0) {
            const int r = rg * 16 + g;
            smin[ne * TILE + r]     = m0;
            smin[ne * TILE + r + 8] = m1;
        }
        __syncthreads();   // sync1: smin, norms, rcnt/rbest ready

        // ---- thresholds (32 threads), rigorous C-S bound ----
        if (tid < TILE) {
            float minest = FLT_MAX;
            #pragma unroll
            for (int e = 0; e < 8; e++) minest = fminf(minest, smin[e * TILE + tid]);
            float xns = sqrtf(sxn[tid]), rxs = sqrtf(srx[tid]);
            float bnd = 2.f * (rxs * (S_h + S_e) + (xns + rxs) * S_e);
            sthr[tid] = minest + 2.f * bnd + 0.20f;   // slack + fp16 round guard
        }
        __syncthreads();   // sync2: sthr ready

        // ---- Scan: in-register tests, rare-path append ----
        {
            const int r0 = rg * 16 + g;
            const __half2 thr2a = __float2half2_rn(sthr[r0]);
            const __half2 thr2b = __float2half2_rn(sthr[r0 + 8]);
            #pragma unroll
            for (int j = 0; j < 8; j++) {
                const int kb = (ntbeg + j) * 8 + 2 * c;
                test_h2(estp[2 * j],     thr2a, kb, r0,     rcnt, swl);
                test_h2(estp[2 * j + 1], thr2b, kb, r0 + 8, rcnt, swl);
            }
        }
        __syncthreads();   // sync3: worklists complete

        // ---- Rescore: exactly 1 slot per thread, u64 atomicMin ----
        {
            const int row  = tid >> 4;           // 0..31
            const int slot = tid & (CAP - 1);
            int cnt = rcnt[row]; if (cnt > CAP) cnt = CAP;
            if (slot < cnt) {
                const int k = swl[row * CAP + slot];
                float s = exact_dist(x + (size_t)(tile * TILE + row) * D_DIM, k);
                unsigned long long key =
                    ((unsigned long long)(unsigned)__float_as_int(s) << 32) | (unsigned)k;
                atomicMin(&rbest[row], key);
            }
        }
        // overflow fallback (provably correct; practically never taken)
        #pragma unroll 1
        for (int rr = 0; rr < 2; rr++) {
            const int row = w * 2 + rr;
            if (rcnt[row] > CAP) {
                const float* xrow = x + (size_t)(tile * TILE + row) * D_DIM;
                for (int k = lane; k < K_CODES; k += 32) {
                    float s = exact_dist(xrow, k);
                    unsigned long long key =
                        ((unsigned long long)(unsigned)__float_as_int(s) << 32) | (unsigned)k;
                    atomicMin(&rbest[row], key);
                }
            }
        }
        __syncthreads();   // sync4: rbest final

        // ---- output + loss: 16 threads per row, 1 float4 each ----
        {
            const int r = tid >> 4;              // 0..31
            const int q = tid & 15;
            unsigned long long key = rbest[r];
            const int k = (int)(unsigned)key;
            double dloc = (q == 0) ? (double)__int_as_float((int)(key >> 32)) : 0.0;
            const float4* src = (const float4*)(g_embT + k * D_DIM);
            float4* dst = (float4*)(out + (size_t)(tile * TILE + r) * D_DIM);
            dst[q] = src[q];
            dloc += __shfl_down_sync(0xffffffffu, dloc, 16);
            if (lane == 0) sls[w] = dloc;
        }
        __syncthreads();   // sync5: sls ready; state reusable

        if (tid == 0) {
            double t = 0.0;
            #pragma unroll
            for (int i = 0; i < 16; i++) t += sls[i];
            lacc += t;
        }
    }

    // ---- loss: per-CTA partial -> last block finalizes ----
    if (tid == 0) {
        g_partial[blockIdx.x] = lacc;
        __threadfence();
        unsigned n = atomicAdd(&g_cnt, 1u);
        if (n == GRID - 1) {
            __threadfence();
            double tot = 0.0;
            for (int i = 0; i < GRID; i++) tot += g_partial[i];
            if (write_loss)
                out[(size_t)NROWS * D_DIM] =
                    (float)(tot * (1.25 / ((double)NROWS * (double)D_DIM)));
            g_cnt = 0;   // reset for next graph replay
        }
    }
}

extern "C" void kernel_launch(void* const* d_in, const int* in_sizes, int n_in,
                              void* d_out, int out_size)
{
    const float* x   = (const float*)d_in[0];
    const float* emb = (const float*)d_in[1];
    float* out = (float*)d_out;

    const int write_loss = (out_size > NROWS * D_DIM) ? 1 : 0;

    static int configured = 0;
    if (!configured) {
        cudaFuncSetAttribute(vq_2stage, cudaFuncAttributeMaxDynamicSharedMemorySize, SMEM_TOTAL);
        configured = 1;
    }
    vq_2stage<<<GRID, BLOCK, SMEM_TOTAL>>>(x, emb, out, write_loss);
}

// round 14
// speedup vs baseline: 1.1952x; 1.1952x over previous
#include <cuda_runtime.h>
#include <cuda_bf16.h>
#include <cuda_fp16.h>
#include <float.h>
#include <stdint.h>

#define D_DIM   64
#define K_CODES 512
#define BLOCK   512          // 16 warps: 4 row-groups x 4 code-quarters
#define GRID    148
#define NROWS   65536
#define TILE    64           // rows per tile
#define NTILES  1024
#define CAP     16           // worklist slots per row

// ---- SMEM layout (bytes), ~71KB, 1 CTA/SM ----
#define SM_BH    0            // 8192 uint2 hi-bf16 B fragments (64KB)
#define SM_SN    65536        // 512 floats: exact ||e_k||^2
#define SM_SMIN  67584        // 4*64 floats: per-quarter row min
#define SM_SXN   68608        // 64 floats: ||x_r||^2
#define SM_SRX   68864        // 64 floats: ||x_r - xh_r||^2
#define SM_RCNT  69120        // 64 ints
#define SM_RBEST 69376        // 64 u64
#define SM_WL    69888        // 64*CAP ints (4KB)
#define SM_SE2   73984        // int
#define SM_SH2   73988        // int
#define SM_LS    73992        // 16 doubles
#define SMEM_TOTAL 74120

__device__ float        g_embT[K_CODES * D_DIM];   // exact fp32 codebook [k][d]
__device__ double       g_partial[GRID];
__device__ unsigned int g_cnt = 0;

#define MMA(acc, a, b0, b1)                                                     \
    asm volatile(                                                               \
        "mma.sync.aligned.m16n8k16.row.col.f32.bf16.bf16.f32 "                  \
        "{%0,%1,%2,%3}, {%4,%5,%6,%7}, {%8,%9}, {%0,%1,%2,%3};"                 \
        : "+f"((acc)[0]), "+f"((acc)[1]), "+f"((acc)[2]), "+f"((acc)[3])        \
        : "r"((a)[0]), "r"((a)[1]), "r"((a)[2]), "r"((a)[3]), "r"(b0), "r"(b1))

__device__ __forceinline__ uint32_t pack_bf2(float a, float b) {
    return (uint32_t)__bfloat16_as_ushort(__float2bfloat16(a))
         | ((uint32_t)__bfloat16_as_ushort(__float2bfloat16(b)) << 16);
}

// exact fp32 squared distance row(x) vs code k (fixed summation order)
__device__ __forceinline__ float exact_dist(const float* __restrict__ xrow, int k) {
    const float4* xp = (const float4*)xrow;
    const float4* ep = (const float4*)(g_embT + k * D_DIM);
    float s = 0.f;
    #pragma unroll
    for (int j = 0; j < 16; j++) {
        float4 a = xp[j];
        float4 b = ep[j];
        float dx = a.x - b.x, dy = a.y - b.y, dz = a.z - b.z, dw = a.w - b.w;
        s = fmaf(dx, dx, s); s = fmaf(dy, dy, s);
        s = fmaf(dz, dz, s); s = fmaf(dw, dw, s);
    }
    return s;
}

// test one packed half2 estimate vs threshold; append passing codes (rare path)
__device__ __forceinline__ void test_h2(uint32_t h2bits, __half2 thr2, int kbase,
                                        int row, int* rcnt, int* swl) {
    __half2 v  = *(__half2*)&h2bits;
    __half2 le = __hle2(v, thr2);
    uint32_t m = *(uint32_t*)&le;
    if (m) {
        if (m & 0xFFFFu) {
            int s = atomicAdd(&rcnt[row], 1);
            if (s < CAP) swl[row * CAP + s] = kbase;
        }
        if (m >> 16) {
            int s = atomicAdd(&rcnt[row], 1);
            if (s < CAP) swl[row * CAP + s] = kbase + 1;
        }
    }
}

__global__ void __launch_bounds__(BLOCK, 1)
vq_2stage(const float* __restrict__ x, const float* __restrict__ emb,
          float* __restrict__ out, int write_loss)
{
    extern __shared__ char smem[];
    uint2*              sBH   = (uint2*)(smem + SM_BH);
    float*              snm   = (float*)(smem + SM_SN);
    float*              smin  = (float*)(smem + SM_SMIN);
    float*              sxn   = (float*)(smem + SM_SXN);
    float*              srx   = (float*)(smem + SM_SRX);
    int*                rcnt  = (int*)(smem + SM_RCNT);
    unsigned long long* rbest = (unsigned long long*)(smem + SM_RBEST);
    int*                swl   = (int*)(smem + SM_WL);
    int*                sSE2  = (int*)(smem + SM_SE2);
    int*                sSH2  = (int*)(smem + SM_SH2);
    double*             sls   = (double*)(smem + SM_LS);

    const int tid  = threadIdx.x;
    const int w    = tid >> 5;
    const int lane = tid & 31;
    const int g    = lane >> 2;
    const int c    = lane & 3;
    const int rg   = w & 3;      // row-group (16 rows)
    const int nq   = w >> 2;     // code-quarter: [nq*128, +128)

    if (tid < 2) { sSE2[0] = 0; sSH2[0] = 0; }
    __syncthreads();

    // ---- Prologue 1: hi-bf16 B fragments -> SMEM + exact fp32 transpose ----
    for (int i = tid; i < 8192; i += BLOCK) {
        int nt = i >> 7;
        int ks = (i >> 5) & 3;
        int ln = i & 31;
        int fg = ln >> 2, fc = ln & 3;
        int n  = nt * 8 + fg;
        int d0 = ks * 16 + fc * 2;
        float e00 = __ldg(emb + (d0 + 0) * K_CODES + n);
        float e01 = __ldg(emb + (d0 + 1) * K_CODES + n);
        float e10 = __ldg(emb + (d0 + 8) * K_CODES + n);
        float e11 = __ldg(emb + (d0 + 9) * K_CODES + n);
        sBH[i] = make_uint2(pack_bf2(e00, e01), pack_bf2(e10, e11));
        g_embT[n * D_DIM + d0]     = e00;
        g_embT[n * D_DIM + d0 + 1] = e01;
        g_embT[n * D_DIM + d0 + 8] = e10;
        g_embT[n * D_DIM + d0 + 9] = e11;
    }
    // ---- Prologue 2: exact code norms + split-error maxima ----
    {
        const int k = tid;   // 512 == BLOCK
        float sn = 0.f, se = 0.f, sh = 0.f;
        #pragma unroll 8
        for (int d = 0; d < D_DIM; d++) {
            float v = emb[d * K_CODES + k];
            float h = __bfloat162float(__float2bfloat16(v));
            float r = v - h;
            sn = fmaf(v, v, sn);
            se = fmaf(r, r, se);
            sh = fmaf(h, h, sh);
        }
        snm[k] = sn;
        atomicMax(sSE2, __float_as_int(se));   // nonneg: int cmp == float cmp
        atomicMax(sSH2, __float_as_int(sh));
    }
    __syncthreads();

    const float S_e = sqrtf(__int_as_float(*sSE2)) * 1.0001f;  // max ||e-eh||
    const float S_h = sqrtf(__int_as_float(*sSH2)) * 1.0001f;  // max ||eh||

    double lacc = 0.0;

    for (int tile = blockIdx.x; tile < NTILES; tile += GRID) {
        const int rbase = tile * TILE + rg * 16 + g;

        if (tid < TILE) { rcnt[tid] = 0; rbest[tid] = ~0ull; }

        // ---- A fragments (hi split); norms only from nq==0 warps ----
        uint32_t Ah[4][4];
        float xn0 = 0.f, xn1 = 0.f, rx0 = 0.f, rx1 = 0.f;
        {
            const float* xr0 = x + (size_t)rbase * D_DIM;
            const float* xr1 = xr0 + 8 * D_DIM;
            #pragma unroll
            for (int ks = 0; ks < 4; ks++) {
                #pragma unroll
                for (int p = 0; p < 2; p++) {
                    int col = 2 * c + 8 * p + 16 * ks;
                    float2 v0 = *(const float2*)(xr0 + col);
                    float2 v1 = *(const float2*)(xr1 + col);
                    Ah[ks][2 * p]     = pack_bf2(v0.x, v0.y);
                    Ah[ks][2 * p + 1] = pack_bf2(v1.x, v1.y);
                    if (nq == 0) {
                        xn0 = fmaf(v0.x, v0.x, fmaf(v0.y, v0.y, xn0));
                        xn1 = fmaf(v1.x, v1.x, fmaf(v1.y, v1.y, xn1));
                        float h0x = __bfloat162float(__float2bfloat16(v0.x));
                        float h0y = __bfloat162float(__float2bfloat16(v0.y));
                        float h1x = __bfloat162float(__float2bfloat16(v1.x));
                        float h1y = __bfloat162float(__float2bfloat16(v1.y));
                        float r0x = v0.x - h0x, r0y = v0.y - h0y;
                        float r1x = v1.x - h1x, r1y = v1.y - h1y;
                        rx0 = fmaf(r0x, r0x, fmaf(r0y, r0y, rx0));
                        rx1 = fmaf(r1x, r1x, fmaf(r1y, r1y, rx1));
                    }
                }
            }
        }
        if (nq == 0) {
            #pragma unroll
            for (int off = 1; off <= 2; off <<= 1) {
                xn0 += __shfl_xor_sync(0xffffffffu, xn0, off);
                xn1 += __shfl_xor_sync(0xffffffffu, xn1, off);
                rx0 += __shfl_xor_sync(0xffffffffu, rx0, off);
                rx1 += __shfl_xor_sync(0xffffffffu, rx1, off);
            }
            if (c == 0) {
                const int r = rg * 16 + g;
                sxn[r] = xn0;  sxn[r + 8] = xn1;
                srx[r] = rx0;  srx[r + 8] = rx1;
            }
        }

        // ---- Stage A: est distances (hi-hi term) -> REGISTERS + row min ----
        uint32_t estp[32];           // 16 nt x {row r0 pair, row r0+8 pair}
        float m0 = FLT_MAX, m1 = FLT_MAX;
        const int ntbeg = nq * 16;
        #pragma unroll
        for (int j0 = 0; j0 < 16; j0 += 2) {
            float acc[2][4];
            #pragma unroll
            for (int u = 0; u < 2; u++)
                #pragma unroll
                for (int r = 0; r < 4; r++) acc[u][r] = 0.f;

            #pragma unroll
            for (int ks = 0; ks < 4; ks++)
                #pragma unroll
                for (int u = 0; u < 2; u++) {
                    uint2 b = sBH[((ntbeg + j0 + u) * 4 + ks) * 32 + lane];
                    MMA(acc[u], Ah[ks], b.x, b.y);
                }

            #pragma unroll
            for (int u = 0; u < 2; u++) {
                const int kb = (ntbeg + j0 + u) * 8 + 2 * c;
                float2 s2 = *(const float2*)(snm + kb);
                float e00 = fmaf(-2.f, acc[u][0], s2.x);
                float e01 = fmaf(-2.f, acc[u][1], s2.y);
                float e10 = fmaf(-2.f, acc[u][2], s2.x);
                float e11 = fmaf(-2.f, acc[u][3], s2.y);
                m0 = fminf(m0, fminf(e00, e01));
                m1 = fminf(m1, fminf(e10, e11));
                __half2 p0 = __floats2half2_rn(e00, e01);
                __half2 p1 = __floats2half2_rn(e10, e11);
                estp[2 * (j0 + u)]     = *(uint32_t*)&p0;
                estp[2 * (j0 + u) + 1] = *(uint32_t*)&p1;
            }
        }
        #pragma unroll
        for (int off = 1; off <= 2; off <<= 1) {
            m0 = fminf(m0, __shfl_xor_sync(0xffffffffu, m0, off));
            m1 = fminf(m1, __shfl_xor_sync(0xffffffffu, m1, off));
        }
        if (c == 0) {
            const int r = rg * 16 + g;
            smin[nq * TILE + r]     = m0;
            smin[nq * TILE + r + 8] = m1;
        }
        __syncthreads();   // sync1: smin, norms, rcnt/rbest ready

        // ---- Scan: thresholds inline (deterministic per row), in-register tests ----
        {
            const int r0 = rg * 16 + g;
            const int r1 = r0 + 8;
            float me0 = fminf(fminf(smin[r0], smin[TILE + r0]),
                              fminf(smin[2 * TILE + r0], smin[3 * TILE + r0]));
            float me1 = fminf(fminf(smin[r1], smin[TILE + r1]),
                              fminf(smin[2 * TILE + r1], smin[3 * TILE + r1]));
            float xns0 = sqrtf(sxn[r0]), rxs0 = sqrtf(srx[r0]);
            float xns1 = sqrtf(sxn[r1]), rxs1 = sqrtf(srx[r1]);
            // rigorous: |est-true| <= 2(rxs*(S_h+S_e) + (xns+rxs)*S_e)
            float bnd0 = 2.f * (rxs0 * (S_h + S_e) + (xns0 + rxs0) * S_e);
            float bnd1 = 2.f * (rxs1 * (S_h + S_e) + (xns1 + rxs1) * S_e);
            const __half2 thr2a = __float2half2_rn(me0 + 2.f * bnd0 + 0.20f);
            const __half2 thr2b = __float2half2_rn(me1 + 2.f * bnd1 + 0.20f);
            #pragma unroll
            for (int j = 0; j < 16; j++) {
                const int kb = (ntbeg + j) * 8 + 2 * c;
                test_h2(estp[2 * j],     thr2a, kb, r0, rcnt, swl);
                test_h2(estp[2 * j + 1], thr2b, kb, r1, rcnt, swl);
            }
        }
        __syncthreads();   // sync2: worklists complete

        // ---- Rescore: spread candidates over all threads, u64 atomicMin ----
        #pragma unroll
        for (int it = 0; it < (TILE * CAP) / BLOCK; it++) {
            const int idx  = it * BLOCK + tid;
            const int row  = idx >> 4;           // CAP = 16
            const int slot = idx & (CAP - 1);
            int cnt = rcnt[row]; if (cnt > CAP) cnt = CAP;
            if (slot < cnt) {
                const int k = swl[row * CAP + slot];
                float s = exact_dist(x + (size_t)(tile * TILE + row) * D_DIM, k);
                unsigned long long key =
                    ((unsigned long long)(unsigned)__float_as_int(s) << 32) | (unsigned)k;
                atomicMin(&rbest[row], key);
            }
        }
        // overflow fallback (provably correct; practically never taken)
        #pragma unroll 1
        for (int rr = 0; rr < 4; rr++) {
            const int row = w * 4 + rr;
            if (rcnt[row] > CAP) {
                const float* xrow = x + (size_t)(tile * TILE + row) * D_DIM;
                for (int k = lane; k < K_CODES; k += 32) {
                    float s = exact_dist(xrow, k);
                    unsigned long long key =
                        ((unsigned long long)(unsigned)__float_as_int(s) << 32) | (unsigned)k;
                    atomicMin(&rbest[row], key);
                }
            }
        }
        __syncthreads();   // sync3: rbest final

        // ---- output + loss: 8 threads per row, 2 float4 each ----
        {
            const int r = tid >> 3;              // 0..63
            const int q = tid & 7;
            unsigned long long key = rbest[r];
            const int k = (int)(unsigned)key;
            if (q == 0) lacc += (double)__int_as_float((int)(key >> 32));
            const float4* src = (const float4*)(g_embT + k * D_DIM);
            float4* dst = (float4*)(out + (size_t)(tile * TILE + r) * D_DIM);
            dst[q]     = src[q];
            dst[q + 8] = src[q + 8];
        }
        __syncthreads();   // sync4: state reusable next tile
    }

    // ---- loss: warp reduce -> CTA partial -> last block finalizes ----
    #pragma unroll
    for (int off = 16; off > 0; off >>= 1)
        lacc += __shfl_down_sync(0xffffffffu, lacc, off);
    if (lane == 0) sls[w] = lacc;
    __syncthreads();
    if (tid == 0) {
        double t = 0.0;
        #pragma unroll
        for (int i = 0; i < 16; i++) t += sls[i];
        g_partial[blockIdx.x] = t;
        __threadfence();
        unsigned n = atomicAdd(&g_cnt, 1u);
        if (n == GRID - 1) {
            __threadfence();
            double tot = 0.0;
            for (int i = 0; i < GRID; i++) tot += g_partial[i];
            if (write_loss)
                out[(size_t)NROWS * D_DIM] =
                    (float)(tot * (1.25 / ((double)NROWS * (double)D_DIM)));
            g_cnt = 0;   // reset for next graph replay
        }
    }
}

extern "C" void kernel_launch(void* const* d_in, const int* in_sizes, int n_in,
                              void* d_out, int out_size)
{
    const float* x   = (const float*)d_in[0];
    const float* emb = (const float*)d_in[1];
    float* out = (float*)d_out;

    const int write_loss = (out_size > NROWS * D_DIM) ? 1 : 0;

    static int configured = 0;
    if (!configured) {
        cudaFuncSetAttribute(vq_2stage, cudaFuncAttributeMaxDynamicSharedMemorySize, SMEM_TOTAL);
        configured = 1;
    }
    vq_2stage<<<GRID, BLOCK, SMEM_TOTAL>>>(x, emb, out, write_loss);
}

// round 15
// speedup vs baseline: 1.4179x; 1.1863x over previous
#include <cuda_runtime.h>
#include <cuda_bf16.h>
#include <float.h>
#include <stdint.h>

#define D_DIM   64
#define K_CODES 512
#define BLOCK   512          // 16 autonomous warps
#define GRID    148
#define NROWS   65536
#define NGROUPS 4096         // 16-row groups
#define NWARPS  (GRID * 16)
#define WLCAP   128          // worklist slots per warp

// ---- SMEM layout (bytes), ~78KB, 1 CTA/SM ----
#define SM_BH    0            // 8192 uint2 hi-bf16 B fragments (64KB)
#define SM_SN    65536        // 512 floats: exact ||e_k||^2
#define SM_WL    67584        // 16 warps * 128 ints (8KB)
#define SM_WBEST 75776        // 16 warps * 16 u64 (2KB)
#define SM_WCNT  77824        // 16 ints
#define SM_SE2   77888        // int
#define SM_SH2   77892        // int
#define SM_LS    77896        // 16 doubles
#define SMEM_TOTAL 78024

__device__ float        g_embT[K_CODES * D_DIM];   // exact fp32 codebook [k][d]
__device__ double       g_group_sum[NGROUPS];      // per-group loss partials
__device__ unsigned int g_cnt   = 0;
__device__ unsigned int g_wnext = NWARPS;

#define MMA(acc, a, b0, b1)                                                     \
    asm volatile(                                                               \
        "mma.sync.aligned.m16n8k16.row.col.f32.bf16.bf16.f32 "                  \
        "{%0,%1,%2,%3}, {%4,%5,%6,%7}, {%8,%9}, {%0,%1,%2,%3};"                 \
        : "+f"((acc)[0]), "+f"((acc)[1]), "+f"((acc)[2]), "+f"((acc)[3])        \
        : "r"((a)[0]), "r"((a)[1]), "r"((a)[2]), "r"((a)[3]), "r"(b0), "r"(b1))

__device__ __forceinline__ uint32_t pack_bf2(float a, float b) {
    return (uint32_t)__bfloat16_as_ushort(__float2bfloat16(a))
         | ((uint32_t)__bfloat16_as_ushort(__float2bfloat16(b)) << 16);
}

// exact fp32 squared distance row(x) vs code k (fixed summation order)
__device__ __forceinline__ float exact_dist(const float* __restrict__ xrow, int k) {
    const float4* xp = (const float4*)xrow;
    const float4* ep = (const float4*)(g_embT + k * D_DIM);
    float s = 0.f;
    #pragma unroll
    for (int j = 0; j < 16; j++) {
        float4 a = xp[j];
        float4 b = ep[j];
        float dx = a.x - b.x, dy = a.y - b.y, dz = a.z - b.z, dw = a.w - b.w;
        s = fmaf(dx, dx, s); s = fmaf(dy, dy, s);
        s = fmaf(dz, dz, s); s = fmaf(dw, dw, s);
    }
    return s;
}

__global__ void __launch_bounds__(BLOCK, 1)
vq_wa(const float* __restrict__ x, const float* __restrict__ emb,
      float* __restrict__ out, int write_loss)
{
    extern __shared__ char smem[];
    uint2*              sBH   = (uint2*)(smem + SM_BH);
    float*              snm   = (float*)(smem + SM_SN);
    int*                swl   = (int*)(smem + SM_WL);
    unsigned long long* wbest = (unsigned long long*)(smem + SM_WBEST);
    int*                wcnt  = (int*)(smem + SM_WCNT);
    int*                sSE2  = (int*)(smem + SM_SE2);
    int*                sSH2  = (int*)(smem + SM_SH2);
    double*             sls   = (double*)(smem + SM_LS);

    const int tid  = threadIdx.x;
    const int w    = tid >> 5;
    const int lane = tid & 31;
    const int g    = lane >> 2;
    const int c    = lane & 3;

    if (tid < 2) { sSE2[0] = 0; sSH2[0] = 0; }
    __syncthreads();

    // ---- Prologue 1: hi-bf16 B fragments -> SMEM + exact fp32 transpose ----
    for (int i = tid; i < 8192; i += BLOCK) {
        int nt = i >> 7;
        int ks = (i >> 5) & 3;
        int ln = i & 31;
        int fg = ln >> 2, fc = ln & 3;
        int n  = nt * 8 + fg;
        int d0 = ks * 16 + fc * 2;
        float e00 = __ldg(emb + (d0 + 0) * K_CODES + n);
        float e01 = __ldg(emb + (d0 + 1) * K_CODES + n);
        float e10 = __ldg(emb + (d0 + 8) * K_CODES + n);
        float e11 = __ldg(emb + (d0 + 9) * K_CODES + n);
        sBH[i] = make_uint2(pack_bf2(e00, e01), pack_bf2(e10, e11));
        g_embT[n * D_DIM + d0]     = e00;
        g_embT[n * D_DIM + d0 + 1] = e01;
        g_embT[n * D_DIM + d0 + 8] = e10;
        g_embT[n * D_DIM + d0 + 9] = e11;
    }
    // ---- Prologue 2: exact code norms + split-error maxima ----
    {
        const int k = tid;   // 512 == BLOCK
        float sn = 0.f, se = 0.f, sh = 0.f;
        #pragma unroll 8
        for (int d = 0; d < D_DIM; d++) {
            float v = emb[d * K_CODES + k];
            float h = __bfloat162float(__float2bfloat16(v));
            float r = v - h;
            sn = fmaf(v, v, sn);
            se = fmaf(r, r, se);
            sh = fmaf(h, h, sh);
        }
        snm[k] = sn;
        atomicMax(sSE2, __float_as_int(se));   // nonneg: int cmp == float cmp
        atomicMax(sSH2, __float_as_int(sh));
    }
    __syncthreads();   // the ONLY CTA barrier before the epilogue

    const float S_e = sqrtf(__int_as_float(*sSE2)) * 1.0001f;  // max ||e-eh||
    const float S_h = sqrtf(__int_as_float(*sSH2)) * 1.0001f;  // max ||eh||

    const int gwid = blockIdx.x * 16 + w;
    int grp = gwid;
    int nextg = 0;

    while (grp < NGROUPS) {
        const int rbase = grp * 16;

        // warp-private state init
        if (lane < 16) wbest[w * 16 + lane] = ~0ull;
        if (lane == 0) wcnt[w] = 0;

        // ---- A fragments (hi split) + per-row norm / residual-norm ----
        uint32_t Ah[4][4];
        float xn0 = 0.f, xn1 = 0.f, rx0 = 0.f, rx1 = 0.f;
        {
            const float* xr0 = x + (size_t)(rbase + g) * D_DIM;
            const float* xr1 = xr0 + 8 * D_DIM;
            #pragma unroll
            for (int ks = 0; ks < 4; ks++) {
                #pragma unroll
                for (int p = 0; p < 2; p++) {
                    int col = 2 * c + 8 * p + 16 * ks;
                    float2 v0 = *(const float2*)(xr0 + col);
                    float2 v1 = *(const float2*)(xr1 + col);
                    xn0 = fmaf(v0.x, v0.x, fmaf(v0.y, v0.y, xn0));
                    xn1 = fmaf(v1.x, v1.x, fmaf(v1.y, v1.y, xn1));
                    float h0x = __bfloat162float(__float2bfloat16(v0.x));
                    float h0y = __bfloat162float(__float2bfloat16(v0.y));
                    float h1x = __bfloat162float(__float2bfloat16(v1.x));
                    float h1y = __bfloat162float(__float2bfloat16(v1.y));
                    float r0x = v0.x - h0x, r0y = v0.y - h0y;
                    float r1x = v1.x - h1x, r1y = v1.y - h1y;
                    rx0 = fmaf(r0x, r0x, fmaf(r0y, r0y, rx0));
                    rx1 = fmaf(r1x, r1x, fmaf(r1y, r1y, rx1));
                    Ah[ks][2 * p]     = pack_bf2(v0.x, v0.y);
                    Ah[ks][2 * p + 1] = pack_bf2(v1.x, v1.y);
                }
            }
        }
        #pragma unroll
        for (int off = 1; off <= 2; off <<= 1) {
            xn0 += __shfl_xor_sync(0xffffffffu, xn0, off);
            xn1 += __shfl_xor_sync(0xffffffffu, xn1, off);
            rx0 += __shfl_xor_sync(0xffffffffu, rx0, off);
            rx1 += __shfl_xor_sync(0xffffffffu, rx1, off);
        }

        // ---- Pass 1: all 512 est distances, track row min only ----
        float m0 = FLT_MAX, m1 = FLT_MAX;
        #pragma unroll 4
        for (int nt = 0; nt < 64; nt++) {
            float acc[4] = {0.f, 0.f, 0.f, 0.f};
            #pragma unroll
            for (int ks = 0; ks < 4; ks++) {
                uint2 b = sBH[(nt * 4 + ks) * 32 + lane];
                MMA(acc, Ah[ks], b.x, b.y);
            }
            const int kb = nt * 8 + 2 * c;
            float2 s2 = *(const float2*)(snm + kb);
            m0 = fminf(m0, fminf(fmaf(-2.f, acc[0], s2.x), fmaf(-2.f, acc[1], s2.y)));
            m1 = fminf(m1, fminf(fmaf(-2.f, acc[2], s2.x), fmaf(-2.f, acc[3], s2.y)));
        }
        #pragma unroll
        for (int off = 1; off <= 2; off <<= 1) {
            m0 = fminf(m0, __shfl_xor_sync(0xffffffffu, m0, off));
            m1 = fminf(m1, __shfl_xor_sync(0xffffffffu, m1, off));
        }

        // ---- per-row thresholds (fp32, rigorous C-S bound) ----
        float xns0 = sqrtf(xn0), rxs0 = sqrtf(rx0);
        float xns1 = sqrtf(xn1), rxs1 = sqrtf(rx1);
        const float thr0 = m0 + 4.f * (rxs0 * (S_h + S_e) + (xns0 + rxs0) * S_e) + 0.05f;
        const float thr1 = m1 + 4.f * (rxs1 * (S_h + S_e) + (xns1 + rxs1) * S_e) + 0.05f;

        __syncwarp();   // wbest/wcnt init visible

        // ---- Pass 2: recompute (bitwise-identical), append candidates ----
        #pragma unroll 4
        for (int nt = 0; nt < 64; nt++) {
            float acc[4] = {0.f, 0.f, 0.f, 0.f};
            #pragma unroll
            for (int ks = 0; ks < 4; ks++) {
                uint2 b = sBH[(nt * 4 + ks) * 32 + lane];
                MMA(acc, Ah[ks], b.x, b.y);
            }
            const int kb = nt * 8 + 2 * c;
            float2 s2 = *(const float2*)(snm + kb);
            float e00 = fmaf(-2.f, acc[0], s2.x);
            float e01 = fmaf(-2.f, acc[1], s2.y);
            float e10 = fmaf(-2.f, acc[2], s2.x);
            float e11 = fmaf(-2.f, acc[3], s2.y);
            if (e00 <= thr0 || e01 <= thr0 || e10 <= thr1 || e11 <= thr1) {
                if (e00 <= thr0) {
                    int s = atomicAdd(&wcnt[w], 1);
                    if (s < WLCAP) swl[w * WLCAP + s] = (g << 9) | kb;
                }
                if (e01 <= thr0) {
                    int s = atomicAdd(&wcnt[w], 1);
                    if (s < WLCAP) swl[w * WLCAP + s] = (g << 9) | (kb + 1);
                }
                if (e10 <= thr1) {
                    int s = atomicAdd(&wcnt[w], 1);
                    if (s < WLCAP) swl[w * WLCAP + s] = ((g + 8) << 9) | kb;
                }
                if (e11 <= thr1) {
                    int s = atomicAdd(&wcnt[w], 1);
                    if (s < WLCAP) swl[w * WLCAP + s] = ((g + 8) << 9) | (kb + 1);
                }
            }
        }
        __syncwarp();   // worklist complete

        // ---- Rescore: warp-parallel exact fp32, u64 atomicMin ----
        int cnt = wcnt[w];
        if (cnt <= WLCAP) {
            for (int i = lane; i < cnt; i += 32) {
                const int pk   = swl[w * WLCAP + i];
                const int rloc = pk >> 9;
                const int k    = pk & (K_CODES - 1);
                float s = exact_dist(x + (size_t)(rbase + rloc) * D_DIM, k);
                unsigned long long key =
                    ((unsigned long long)(unsigned)__float_as_int(s) << 32) | (unsigned)k;
                atomicMin(&wbest[w * 16 + rloc], key);
            }
        } else {   // provably-correct fallback; practically never taken
            for (int rloc = 0; rloc < 16; rloc++) {
                const float* xrow = x + (size_t)(rbase + rloc) * D_DIM;
                for (int k = lane; k < K_CODES; k += 32) {
                    float s = exact_dist(xrow, k);
                    unsigned long long key =
                        ((unsigned long long)(unsigned)__float_as_int(s) << 32) | (unsigned)k;
                    atomicMin(&wbest[w * 16 + rloc], key);
                }
            }
        }
        __syncwarp();   // wbest final

        // ---- output + group loss: lane L -> row L>>1, half L&1 ----
        {
            const int rloc = lane >> 1;
            const int half = lane & 1;
            unsigned long long key = wbest[w * 16 + rloc];
            const int k = (int)(unsigned)key;
            double dloc = (half == 0) ? (double)__int_as_float((int)(key >> 32)) : 0.0;
            const float4* src = (const float4*)(g_embT + k * D_DIM) + half * 8;
            float4* dst = (float4*)(out + (size_t)(rbase + rloc) * D_DIM) + half * 8;
            #pragma unroll
            for (int j = 0; j < 8; j++) dst[j] = src[j];
            #pragma unroll
            for (int off = 16; off > 0; off >>= 1)
                dloc += __shfl_down_sync(0xffffffffu, dloc, off);
            if (lane == 0) {
                g_group_sum[grp] = dloc;
                nextg = (int)atomicAdd(&g_wnext, 1u);   // steal next group
            }
        }
        grp = __shfl_sync(0xffffffffu, nextg, 0);
        __syncwarp();   // wbest/wcnt reusable next group
    }

    // ---- finalize: last CTA reduces per-group sums in fixed order ----
    __syncthreads();
    __threadfence();
    if (tid == 0) sSE2[0] = (atomicAdd(&g_cnt, 1u) == GRID - 1) ? 1 : 0;
    __syncthreads();
    if (sSE2[0]) {
        __threadfence();
        double s = 0.0;
        #pragma unroll
        for (int i = 0; i < NGROUPS / BLOCK; i++)
            s += g_group_sum[tid + i * BLOCK];
        #pragma unroll
        for (int off = 16; off > 0; off >>= 1)
            s += __shfl_down_sync(0xffffffffu, s, off);
        if (lane == 0) sls[w] = s;
        __syncthreads();
        if (tid == 0) {
            double tot = 0.0;
            #pragma unroll
            for (int i = 0; i < 16; i++) tot += sls[i];
            if (write_loss)
                out[(size_t)NROWS * D_DIM] =
                    (float)(tot * (1.25 / ((double)NROWS * (double)D_DIM)));
            g_cnt   = 0;        // reset for next graph replay
            g_wnext = NWARPS;
        }
    }
}

extern "C" void kernel_launch(void* const* d_in, const int* in_sizes, int n_in,
                              void* d_out, int out_size)
{
    const float* x   = (const float*)d_in[0];
    const float* emb = (const float*)d_in[1];
    float* out = (float*)d_out;

    const int write_loss = (out_size > NROWS * D_DIM) ? 1 : 0;

    static int configured = 0;
    if (!configured) {
        cudaFuncSetAttribute(vq_wa, cudaFuncAttributeMaxDynamicSharedMemorySize, SMEM_TOTAL);
        configured = 1;
    }
    vq_wa<<<GRID, BLOCK, SMEM_TOTAL>>>(x, emb, out, write_loss);
}